// round 10
// baseline (speedup 1.0000x reference)
#include <cuda_runtime.h>

#define NT 128           // threads per block (one batch row per thread)
#define BTOT 32768
typedef unsigned long long u64;

// ---------------- scratch (allocation-free rule: __device__ globals) --------
static __device__ float g_hq[BTOT * 4];
static __device__ float g_hp[BTOT * 4];

// ---------------- f32x2 helpers ---------------------------------------------
__device__ __forceinline__ u64 splat2(float x) {
    u64 r;
    // volatile: force rematerialization inside the tile loop (reg pressure)
    asm volatile("mov.b64 %0, {%1, %1};" : "=l"(r) : "f"(x));
    return r;
}
__device__ __forceinline__ u64 fma2(u64 a, u64 b, u64 c) {
    u64 d;
    asm("fma.rn.f32x2 %0, %1, %2, %3;" : "=l"(d) : "l"(a), "l"(b), "l"(c));
    return d;
}
__device__ __forceinline__ void unpack2(u64 v, float& lo, float& hi) {
    asm("mov.b64 {%0, %1}, %2;" : "=f"(lo), "=f"(hi) : "l"(v));
}

// ---------------- fast activations (MUFU-based, ~1e-6 accurate) -------------
__device__ __forceinline__ float sigf(float x) {
    return __fdividef(1.0f, 1.0f + __expf(-x));
}
__device__ __forceinline__ float tanhfast(float x) {
    float e = __expf(2.0f * x);
    return 1.0f - __fdividef(2.0f, e + 1.0f);
}

// ---------------- shared-memory layout (floats) -----------------------------
// weights gate-interleaved: w4[k][j][{i,f,g,o}]  (all offsets 16B-aligned)
static const int OFF_WIH0 = 0;              // 50*25*4 = 5000
static const int OFF_WHH0 = 5000;           // 25*25*4 = 2500
static const int OFF_B0   = 7500;           // 100
static const int OFF_WIH1 = 7600;           // 25*10*4 = 1000
static const int OFF_WHH1 = 8600;           // 10*10*4 = 400
static const int OFF_B1   = 9000;           // 40
static const int OFF_WIH2 = 9040;           // 10*4*4 = 160
static const int OFF_WHH2 = 9200;           // 4*4*4 = 64
static const int OFF_B2   = 9264;           // 16
static const int W_TOTAL  = 9280;
// L0 state columns [elem][NT] (h0: 25, c0: 25); L1/L2 state lives in registers
static const int ST_HS0 = W_TOTAL;
static const int ST_CS0 = W_TOTAL + 25 * NT;
static const int SMEM_FLOATS = W_TOTAL + 50 * NT;            // 15,680
static const int SMEM_BYTES  = SMEM_FLOATS * 4;              // 62,720 -> 3 blocks/SM

// ---------------- weight packers --------------------------------------------
// src Wih: [4H, DIN] row-major (torch gate order i,f,g,o).
// dst[(k*H+j)*4+g] = src[(g*H+j)*DIN+k]
template <int DIN, int H>
__device__ void packw(float* dst, const float* __restrict__ src, int tid) {
    const int n = DIN * H * 4;
    for (int idx = tid; idx < n; idx += NT) {
        int g = idx & 3, jk = idx >> 2;
        int j = jk % H, k = jk / H;
        dst[idx] = src[(g * H + j) * DIN + k];
    }
}
template <int H>
__device__ void packb(float* dst, const float* __restrict__ src, int tid) {
    for (int idx = tid; idx < 4 * H; idx += NT) {
        int g = idx & 3, j = idx >> 2;
        dst[idx] = src[g * H + j];
    }
}

// ---------------- L0 step: x regs, h/c in smem, j-tiled ----------------------
// hs/cs: smem pointers already offset by +tid, element stride NT.
__device__ __forceinline__ void step_l0(
    const float (&xs)[50], float* hs, float* cs, const float* wbase)
{
    float hold[25];
#pragma unroll
    for (int k = 0; k < 25; k++) hold[k] = hs[k * NT];

    const ulonglong2* wih = reinterpret_cast<const ulonglong2*>(wbase + OFF_WIH0);
    const ulonglong2* whh = reinterpret_cast<const ulonglong2*>(wbase + OFF_WHH0);
    const ulonglong2* bb  = reinterpret_cast<const ulonglong2*>(wbase + OFF_B0);

#pragma unroll 1
    for (int jt = 0; jt < 25; jt += 5) {
        u64 a01[5], a23[5];
#pragma unroll
        for (int jj = 0; jj < 5; jj++) {
            ulonglong2 b = bb[jt + jj];
            a01[jj] = b.x;                   // {acc_i, acc_f}
            a23[jj] = b.y;                   // {acc_g, acc_o}
        }
#pragma unroll
        for (int k = 0; k < 50; k++) {
            u64 xv = splat2(xs[k]);
#pragma unroll
            for (int jj = 0; jj < 5; jj++) {
                ulonglong2 w = wih[k * 25 + jt + jj];   // LDS.128 broadcast
                a01[jj] = fma2(xv, w.x, a01[jj]);
                a23[jj] = fma2(xv, w.y, a23[jj]);
            }
        }
#pragma unroll
        for (int k = 0; k < 25; k++) {
            u64 hv = splat2(hold[k]);
#pragma unroll
            for (int jj = 0; jj < 5; jj++) {
                ulonglong2 w = whh[k * 25 + jt + jj];
                a01[jj] = fma2(hv, w.x, a01[jj]);
                a23[jj] = fma2(hv, w.y, a23[jj]);
            }
        }
#pragma unroll
        for (int jj = 0; jj < 5; jj++) {
            float ai, af, ag, ao;
            unpack2(a01[jj], ai, af);
            unpack2(a23[jj], ag, ao);
            float cg = fmaf(sigf(af), cs[(jt + jj) * NT], sigf(ai) * tanhfast(ag));
            cs[(jt + jj) * NT] = cg;
            hs[(jt + jj) * NT] = sigf(ao) * tanhfast(cg);
        }
    }
}

// ---------------- small-layer step: everything in registers, j-tiled --------
template <int DIN, int H, int JB, int NX>
__device__ __forceinline__ void step_small(
    const float (&xs)[NX], float (&h)[H], float (&c)[H],
    const float* swih, const float* swhh, const float* sbias)
{
    float hold[H];
#pragma unroll
    for (int j = 0; j < H; j++) hold[j] = h[j];

    const ulonglong2* wih = reinterpret_cast<const ulonglong2*>(swih);
    const ulonglong2* whh = reinterpret_cast<const ulonglong2*>(swhh);
    const ulonglong2* bb  = reinterpret_cast<const ulonglong2*>(sbias);

#pragma unroll 1
    for (int jt = 0; jt < H; jt += JB) {
        u64 a01[JB], a23[JB];
#pragma unroll
        for (int jj = 0; jj < JB; jj++) {
            ulonglong2 b = bb[jt + jj];
            a01[jj] = b.x;
            a23[jj] = b.y;
        }
#pragma unroll
        for (int k = 0; k < DIN; k++) {
            u64 xv = splat2(xs[k]);
#pragma unroll
            for (int jj = 0; jj < JB; jj++) {
                ulonglong2 w = wih[k * H + jt + jj];
                a01[jj] = fma2(xv, w.x, a01[jj]);
                a23[jj] = fma2(xv, w.y, a23[jj]);
            }
        }
#pragma unroll
        for (int k = 0; k < H; k++) {
            u64 hv = splat2(hold[k]);
#pragma unroll
            for (int jj = 0; jj < JB; jj++) {
                ulonglong2 w = whh[k * H + jt + jj];
                a01[jj] = fma2(hv, w.x, a01[jj]);
                a23[jj] = fma2(hv, w.y, a23[jj]);
            }
        }
#pragma unroll
        for (int jj = 0; jj < JB; jj++) {
            float ai, af, ag, ao;
            unpack2(a01[jj], ai, af);
            unpack2(a23[jj], ag, ao);
            float cg = fmaf(sigf(af), c[jt + jj], sigf(ai) * tanhfast(ag));
            c[jt + jj] = cg;
            h[jt + jj] = sigf(ao) * tanhfast(cg);
        }
    }
}

// ---------------- tower body ------------------------------------------------
template <int T>
__device__ __forceinline__ void run_tower(
    const float* __restrict__ x_in, const float* const* w,
    float* __restrict__ hout, int blockbase, float* sm)
{
    const int tid = threadIdx.x;

    packw<50, 25>(sm + OFF_WIH0, w[0], tid);
    packw<25, 25>(sm + OFF_WHH0, w[1], tid);
    packb<25>(sm + OFF_B0, w[2], tid);
    packw<25, 10>(sm + OFF_WIH1, w[3], tid);
    packw<10, 10>(sm + OFF_WHH1, w[4], tid);
    packb<10>(sm + OFF_B1, w[5], tid);
    packw<10, 4>(sm + OFF_WIH2, w[6], tid);
    packw<4, 4>(sm + OFF_WHH2, w[7], tid);
    packb<4>(sm + OFF_B2, w[8], tid);
    __syncthreads();

    float* hs0 = sm + ST_HS0 + tid;
    float* cs0 = sm + ST_CS0 + tid;
#pragma unroll
    for (int j = 0; j < 25; j++) { hs0[j * NT] = 0.0f; cs0[j * NT] = 0.0f; }

    float h1[10], c1[10], h2[4], c2[4];
#pragma unroll
    for (int j = 0; j < 10; j++) { h1[j] = 0.0f; c1[j] = 0.0f; }
#pragma unroll
    for (int j = 0; j < 4; j++)  { h2[j] = 0.0f; c2[j] = 0.0f; }

    const int row = blockbase * NT + tid;
    const float* xrow = x_in + (size_t)row * T * 50;

#pragma unroll 1
    for (int t = 0; t < T; t++) {
        float xs[50];
        const float2* xp = reinterpret_cast<const float2*>(xrow + t * 50);
#pragma unroll
        for (int k2 = 0; k2 < 25; k2++) {
            float2 v = __ldg(xp + k2);
            xs[2 * k2]     = v.x;
            xs[2 * k2 + 1] = v.y;
        }
        step_l0(xs, hs0, cs0, sm);

        float x1[25];
#pragma unroll
        for (int k = 0; k < 25; k++) x1[k] = hs0[k * NT];
        step_small<25, 10, 5>(x1, h1, c1,
                              sm + OFF_WIH1, sm + OFF_WHH1, sm + OFF_B1);
        step_small<10, 4, 4>(h1, h2, c2,
                             sm + OFF_WIH2, sm + OFF_WHH2, sm + OFF_B2);
    }

#pragma unroll
    for (int j = 0; j < 4; j++) hout[row * 4 + j] = h2[j];
}

// ---------------- merged dual-tower kernel ----------------------------------
__global__ void __launch_bounds__(NT, 3)
towers_kernel(
    const float* __restrict__ q, const float* __restrict__ p,
    const float* qa0, const float* qa1, const float* qa2,
    const float* qa3, const float* qa4, const float* qa5,
    const float* qa6, const float* qa7, const float* qa8,
    const float* pa0, const float* pa1, const float* pa2,
    const float* pa3, const float* pa4, const float* pa5,
    const float* pa6, const float* pa7, const float* pa8)
{
    extern __shared__ float sm[];
    if (blockIdx.x < BTOT / NT) {
        const float* pw[9] = {pa0, pa1, pa2, pa3, pa4, pa5, pa6, pa7, pa8};
        // p tower first (T=50, long blocks start in wave 1)
        run_tower<50>(p, pw, g_hp, blockIdx.x, sm);
    } else {
        const float* qw[9] = {qa0, qa1, qa2, qa3, qa4, qa5, qa6, qa7, qa8};
        run_tower<12>(q, qw, g_hq, blockIdx.x - BTOT / NT, sm);
    }
}

// ---------------- combine: scores -> softmax --------------------------------
__global__ void __launch_bounds__(256)
combine_kernel(const float* __restrict__ fW, const float* __restrict__ fb,
               float* __restrict__ out)
{
    int row = blockIdx.x * blockDim.x + threadIdx.x;
    float s0 = g_hq[row * 4 + 0] * g_hp[row * 4 + 0];
    float s1 = g_hq[row * 4 + 1] * g_hp[row * 4 + 1];
    float s2 = g_hq[row * 4 + 2] * g_hp[row * 4 + 2];
    float s3 = g_hq[row * 4 + 3] * g_hp[row * 4 + 3];
    float l0 = __ldg(fb + 0) + __ldg(fW + 0) * s0 + __ldg(fW + 1) * s1
                             + __ldg(fW + 2) * s2 + __ldg(fW + 3) * s3;
    float l1 = __ldg(fb + 1) + __ldg(fW + 4) * s0 + __ldg(fW + 5) * s1
                             + __ldg(fW + 6) * s2 + __ldg(fW + 7) * s3;
    float m = fmaxf(l0, l1);
    float e0 = __expf(l0 - m);
    float e1 = __expf(l1 - m);
    float inv = __fdividef(1.0f, e0 + e1);
    out[row * 2 + 0] = e0 * inv;
    out[row * 2 + 1] = e1 * inv;
}

// ---------------- launch ----------------------------------------------------
extern "C" void kernel_launch(void* const* d_in, const int* in_sizes, int n_in,
                              void* d_out, int out_size)
{
    const float* q  = (const float*)d_in[0];
    const float* p  = (const float*)d_in[1];
    const float* qw[9];
    const float* pw[9];
    for (int i = 0; i < 9; i++) qw[i] = (const float*)d_in[2 + i];
    for (int i = 0; i < 9; i++) pw[i] = (const float*)d_in[11 + i];
    const float* fW = (const float*)d_in[20];
    const float* fb = (const float*)d_in[21];
    float* out = (float*)d_out;

    cudaFuncSetAttribute(towers_kernel,
                         cudaFuncAttributeMaxDynamicSharedMemorySize, SMEM_BYTES);

    towers_kernel<<<2 * (BTOT / NT), NT, SMEM_BYTES>>>(
        q, p,
        qw[0], qw[1], qw[2], qw[3], qw[4], qw[5], qw[6], qw[7], qw[8],
        pw[0], pw[1], pw[2], pw[3], pw[4], pw[5], pw[6], pw[7], pw[8]);
    combine_kernel<<<BTOT / 256, 256>>>(fW, fb, out);
}

// round 12
// speedup vs baseline: 1.0090x; 1.0090x over previous
#include <cuda_runtime.h>

#define NT 128           // threads per block (one batch row per thread)
#define BTOT 32768
typedef unsigned long long u64;

// ---------------- scratch (allocation-free rule: __device__ globals) --------
static __device__ float g_hq[BTOT * 4];
static __device__ float g_hp[BTOT * 4];

// ---------------- f32x2 helpers (NON-volatile: let the scheduler move them) -
__device__ __forceinline__ u64 splat2(float x) {
    u64 r;
    asm("mov.b64 %0, {%1, %1};" : "=l"(r) : "f"(x));
    return r;
}
__device__ __forceinline__ u64 fma2(u64 a, u64 b, u64 c) {
    u64 d;
    asm("fma.rn.f32x2 %0, %1, %2, %3;" : "=l"(d) : "l"(a), "l"(b), "l"(c));
    return d;
}
__device__ __forceinline__ void unpack2(u64 v, float& lo, float& hi) {
    asm("mov.b64 {%0, %1}, %2;" : "=f"(lo), "=f"(hi) : "l"(v));
}

// ---------------- fast activations (MUFU-based, ~1e-6 accurate) -------------
__device__ __forceinline__ float sigf(float x) {
    return __fdividef(1.0f, 1.0f + __expf(-x));
}
__device__ __forceinline__ float tanhfast(float x) {
    float e = __expf(2.0f * x);
    return 1.0f - __fdividef(2.0f, e + 1.0f);
}

// ---------------- shared-memory layout (floats) -----------------------------
// weights gate-interleaved: w4[k][j][{i,f,g,o}]  (all offsets 16B-aligned)
static const int OFF_WIH0 = 0;              // 50*25*4 = 5000
static const int OFF_WHH0 = 5000;           // 25*25*4 = 2500
static const int OFF_B0   = 7500;           // 100
static const int OFF_WIH1 = 7600;           // 25*10*4 = 1000
static const int OFF_WHH1 = 8600;           // 10*10*4 = 400
static const int OFF_B1   = 9000;           // 40
static const int OFF_WIH2 = 9040;           // 10*4*4 = 160
static const int OFF_WHH2 = 9200;           // 4*4*4 = 64
static const int OFF_B2   = 9264;           // 16
static const int W_TOTAL  = 9280;
// L0 state columns [elem][NT]; L1/L2 state lives in registers
static const int ST_HS0 = W_TOTAL;
static const int ST_CS0 = W_TOTAL + 25 * NT;
static const int SMEM_FLOATS = W_TOTAL + 50 * NT;            // 15,680
static const int SMEM_BYTES  = SMEM_FLOATS * 4;              // 62,720 -> 3 blocks/SM

// ---------------- weight packers --------------------------------------------
// src Wih: [4H, DIN] row-major (torch gate order i,f,g,o).
// dst[(k*H+j)*4+g] = src[(g*H+j)*DIN+k]
template <int DIN, int H>
__device__ void packw(float* dst, const float* __restrict__ src, int tid) {
    const int n = DIN * H * 4;
    for (int idx = tid; idx < n; idx += NT) {
        int g = idx & 3, jk = idx >> 2;
        int j = jk % H, k = jk / H;
        dst[idx] = src[(g * H + j) * DIN + k];
    }
}
template <int H>
__device__ void packb(float* dst, const float* __restrict__ src, int tid) {
    for (int idx = tid; idx < 4 * H; idx += NT) {
        int g = idx & 3, j = idx >> 2;
        dst[idx] = src[g * H + j];
    }
}

// ---------------- L0 step: x regs, h/c in smem, j-tiled (JB=5) ---------------
// hs/cs: smem pointers already offset by +tid, element stride NT.
__device__ __forceinline__ void step_l0(
    const float (&xs)[50], float* hs, float* cs, const float* wbase)
{
    float hold[25];
#pragma unroll
    for (int k = 0; k < 25; k++) hold[k] = hs[k * NT];

    const ulonglong2* wih = reinterpret_cast<const ulonglong2*>(wbase + OFF_WIH0);
    const ulonglong2* whh = reinterpret_cast<const ulonglong2*>(wbase + OFF_WHH0);
    const ulonglong2* bb  = reinterpret_cast<const ulonglong2*>(wbase + OFF_B0);

#pragma unroll 1
    for (int jt = 0; jt < 25; jt += 5) {
        u64 a01[5], a23[5];
#pragma unroll
        for (int jj = 0; jj < 5; jj++) {
            ulonglong2 b = bb[jt + jj];
            a01[jj] = b.x;                   // {acc_i, acc_f}
            a23[jj] = b.y;                   // {acc_g, acc_o}
        }
#pragma unroll
        for (int k = 0; k < 50; k++) {
            u64 xv = splat2(xs[k]);
#pragma unroll
            for (int jj = 0; jj < 5; jj++) {
                ulonglong2 w = wih[k * 25 + jt + jj];   // LDS.128 broadcast
                a01[jj] = fma2(xv, w.x, a01[jj]);
                a23[jj] = fma2(xv, w.y, a23[jj]);
            }
        }
#pragma unroll
        for (int k = 0; k < 25; k++) {
            u64 hv = splat2(hold[k]);
#pragma unroll
            for (int jj = 0; jj < 5; jj++) {
                ulonglong2 w = whh[k * 25 + jt + jj];
                a01[jj] = fma2(hv, w.x, a01[jj]);
                a23[jj] = fma2(hv, w.y, a23[jj]);
            }
        }
#pragma unroll
        for (int jj = 0; jj < 5; jj++) {
            float ai, af, ag, ao;
            unpack2(a01[jj], ai, af);
            unpack2(a23[jj], ag, ao);
            float cg = fmaf(sigf(af), cs[(jt + jj) * NT], sigf(ai) * tanhfast(ag));
            cs[(jt + jj) * NT] = cg;
            hs[(jt + jj) * NT] = sigf(ao) * tanhfast(cg);
        }
    }
}

// ---------------- small-layer step: register state, j-tiled ------------------
template <int DIN, int H, int JB, int NX>
__device__ __forceinline__ void step_small(
    const float (&xs)[NX], float (&h)[H], float (&c)[H],
    const float* swih, const float* swhh, const float* sbias)
{
    float hold[H];
#pragma unroll
    for (int j = 0; j < H; j++) hold[j] = h[j];

    const ulonglong2* wih = reinterpret_cast<const ulonglong2*>(swih);
    const ulonglong2* whh = reinterpret_cast<const ulonglong2*>(swhh);
    const ulonglong2* bb  = reinterpret_cast<const ulonglong2*>(sbias);

#pragma unroll 1
    for (int jt = 0; jt < H; jt += JB) {
        u64 a01[JB], a23[JB];
#pragma unroll
        for (int jj = 0; jj < JB; jj++) {
            ulonglong2 b = bb[jt + jj];
            a01[jj] = b.x;
            a23[jj] = b.y;
        }
#pragma unroll
        for (int k = 0; k < DIN; k++) {
            u64 xv = splat2(xs[k]);
#pragma unroll
            for (int jj = 0; jj < JB; jj++) {
                ulonglong2 w = wih[k * H + jt + jj];
                a01[jj] = fma2(xv, w.x, a01[jj]);
                a23[jj] = fma2(xv, w.y, a23[jj]);
            }
        }
#pragma unroll
        for (int k = 0; k < H; k++) {
            u64 hv = splat2(hold[k]);
#pragma unroll
            for (int jj = 0; jj < JB; jj++) {
                ulonglong2 w = whh[k * H + jt + jj];
                a01[jj] = fma2(hv, w.x, a01[jj]);
                a23[jj] = fma2(hv, w.y, a23[jj]);
            }
        }
#pragma unroll
        for (int jj = 0; jj < JB; jj++) {
            float ai, af, ag, ao;
            unpack2(a01[jj], ai, af);
            unpack2(a23[jj], ag, ao);
            float cg = fmaf(sigf(af), c[jt + jj], sigf(ai) * tanhfast(ag));
            c[jt + jj] = cg;
            h[jt + jj] = sigf(ao) * tanhfast(cg);
        }
    }
}

// ---------------- merged dual-tower kernel (SINGLE code path) ----------------
// Blocks 0..255 run p rows (T=50); blocks 256..511 run q rows (T=12).
// T and pointers are runtime-selected so the tower body exists ONCE in SASS.
__global__ void __launch_bounds__(NT, 3)
towers_kernel(
    const float* __restrict__ q, const float* __restrict__ p,
    const float* qa0, const float* qa1, const float* qa2,
    const float* qa3, const float* qa4, const float* qa5,
    const float* qa6, const float* qa7, const float* qa8,
    const float* pa0, const float* pa1, const float* pa2,
    const float* pa3, const float* pa4, const float* pa5,
    const float* pa6, const float* pa7, const float* pa8)
{
    extern __shared__ float sm[];
    const int tid = threadIdx.x;
    const bool is_p = blockIdx.x < (BTOT / NT);
    const int blockbase = is_p ? blockIdx.x : blockIdx.x - (BTOT / NT);
    const int T = is_p ? 50 : 12;
    const float* x_in = is_p ? p : q;
    float* hout = is_p ? g_hp : g_hq;
    const float* w[9];
    if (is_p) {
        w[0]=pa0; w[1]=pa1; w[2]=pa2; w[3]=pa3; w[4]=pa4;
        w[5]=pa5; w[6]=pa6; w[7]=pa7; w[8]=pa8;
    } else {
        w[0]=qa0; w[1]=qa1; w[2]=qa2; w[3]=qa3; w[4]=qa4;
        w[5]=qa5; w[6]=qa6; w[7]=qa7; w[8]=qa8;
    }

    packw<50, 25>(sm + OFF_WIH0, w[0], tid);
    packw<25, 25>(sm + OFF_WHH0, w[1], tid);
    packb<25>(sm + OFF_B0, w[2], tid);
    packw<25, 10>(sm + OFF_WIH1, w[3], tid);
    packw<10, 10>(sm + OFF_WHH1, w[4], tid);
    packb<10>(sm + OFF_B1, w[5], tid);
    packw<10, 4>(sm + OFF_WIH2, w[6], tid);
    packw<4, 4>(sm + OFF_WHH2, w[7], tid);
    packb<4>(sm + OFF_B2, w[8], tid);
    __syncthreads();

    float* hs0 = sm + ST_HS0 + tid;
    float* cs0 = sm + ST_CS0 + tid;
#pragma unroll
    for (int j = 0; j < 25; j++) { hs0[j * NT] = 0.0f; cs0[j * NT] = 0.0f; }

    float h1[10], c1[10], h2[4], c2[4];
#pragma unroll
    for (int j = 0; j < 10; j++) { h1[j] = 0.0f; c1[j] = 0.0f; }
#pragma unroll
    for (int j = 0; j < 4; j++)  { h2[j] = 0.0f; c2[j] = 0.0f; }

    const int row = blockbase * NT + tid;
    const float* xrow = x_in + (size_t)row * T * 50;

#pragma unroll 1
    for (int t = 0; t < T; t++) {
        float xs[50];
        const float2* xp = reinterpret_cast<const float2*>(xrow + t * 50);
#pragma unroll
        for (int k2 = 0; k2 < 25; k2++) {
            float2 v = __ldg(xp + k2);
            xs[2 * k2]     = v.x;
            xs[2 * k2 + 1] = v.y;
        }
        step_l0(xs, hs0, cs0, sm);

        float x1[25];
#pragma unroll
        for (int k = 0; k < 25; k++) x1[k] = hs0[k * NT];
        step_small<25, 10, 5>(x1, h1, c1,
                              sm + OFF_WIH1, sm + OFF_WHH1, sm + OFF_B1);
        step_small<10, 4, 4>(h1, h2, c2,
                             sm + OFF_WIH2, sm + OFF_WHH2, sm + OFF_B2);
    }

#pragma unroll
    for (int j = 0; j < 4; j++) hout[row * 4 + j] = h2[j];
}

// ---------------- combine: scores -> softmax --------------------------------
__global__ void __launch_bounds__(256)
combine_kernel(const float* __restrict__ fW, const float* __restrict__ fb,
               float* __restrict__ out)
{
    int row = blockIdx.x * blockDim.x + threadIdx.x;
    float s0 = g_hq[row * 4 + 0] * g_hp[row * 4 + 0];
    float s1 = g_hq[row * 4 + 1] * g_hp[row * 4 + 1];
    float s2 = g_hq[row * 4 + 2] * g_hp[row * 4 + 2];
    float s3 = g_hq[row * 4 + 3] * g_hp[row * 4 + 3];
    float l0 = __ldg(fb + 0) + __ldg(fW + 0) * s0 + __ldg(fW + 1) * s1
                             + __ldg(fW + 2) * s2 + __ldg(fW + 3) * s3;
    float l1 = __ldg(fb + 1) + __ldg(fW + 4) * s0 + __ldg(fW + 5) * s1
                             + __ldg(fW + 6) * s2 + __ldg(fW + 7) * s3;
    float m = fmaxf(l0, l1);
    float e0 = __expf(l0 - m);
    float e1 = __expf(l1 - m);
    float inv = __fdividef(1.0f, e0 + e1);
    out[row * 2 + 0] = e0 * inv;
    out[row * 2 + 1] = e1 * inv;
}

// ---------------- launch ----------------------------------------------------
extern "C" void kernel_launch(void* const* d_in, const int* in_sizes, int n_in,
                              void* d_out, int out_size)
{
    const float* q  = (const float*)d_in[0];
    const float* p  = (const float*)d_in[1];
    const float* qw[9];
    const float* pw[9];
    for (int i = 0; i < 9; i++) qw[i] = (const float*)d_in[2 + i];
    for (int i = 0; i < 9; i++) pw[i] = (const float*)d_in[11 + i];
    const float* fW = (const float*)d_in[20];
    const float* fb = (const float*)d_in[21];
    float* out = (float*)d_out;

    cudaFuncSetAttribute(towers_kernel,
                         cudaFuncAttributeMaxDynamicSharedMemorySize, SMEM_BYTES);

    towers_kernel<<<2 * (BTOT / NT), NT, SMEM_BYTES>>>(
        q, p,
        qw[0], qw[1], qw[2], qw[3], qw[4], qw[5], qw[6], qw[7], qw[8],
        pw[0], pw[1], pw[2], pw[3], pw[4], pw[5], pw[6], pw[7], pw[8]);
    combine_kernel<<<BTOT / 256, 256>>>(fW, fb, out);
}

// round 13
// speedup vs baseline: 1.2898x; 1.2783x over previous
#include <cuda_runtime.h>

#define NT 128           // threads per block (one batch row per thread)
#define BTOT 32768
typedef unsigned long long u64;

// ---------------- scratch (allocation-free rule: __device__ globals) --------
static __device__ float g_hq[BTOT * 4];
static __device__ float g_hp[BTOT * 4];

// ---------------- f32x2 helpers ---------------------------------------------
__device__ __forceinline__ u64 splat2(float x) {
    u64 r;
    asm("mov.b64 %0, {%1, %1};" : "=l"(r) : "f"(x));
    return r;
}
__device__ __forceinline__ u64 fma2(u64 a, u64 b, u64 c) {
    u64 d;
    asm("fma.rn.f32x2 %0, %1, %2, %3;" : "=l"(d) : "l"(a), "l"(b), "l"(c));
    return d;
}
__device__ __forceinline__ void unpack2(u64 v, float& lo, float& hi) {
    asm("mov.b64 {%0, %1}, %2;" : "=f"(lo), "=f"(hi) : "l"(v));
}

// ---------------- fast activations (MUFU-based, ~1e-6 accurate) -------------
__device__ __forceinline__ float sigf(float x) {
    return __fdividef(1.0f, 1.0f + __expf(-x));
}
__device__ __forceinline__ float tanhfast(float x) {
    float e = __expf(2.0f * x);
    return 1.0f - __fdividef(2.0f, e + 1.0f);
}

// ---------------- shared-memory layout (floats) -----------------------------
// weights gate-interleaved: w4[k][j][{i,f,g,o}], L0 j-padded to 26 units
// (unit 25 has zero weights/bias; its state slot is write-only garbage).
static const int H0P = 26;
static const int OFF_WIH0 = 0;               // 50*26*4 = 5200
static const int OFF_WHH0 = 5200;            // 25*26*4 = 2600
static const int OFF_B0   = 7800;            // 26*4 = 104
static const int OFF_WIH1 = 7904;            // 25*10*4 = 1000
static const int OFF_WHH1 = 8904;            // 10*10*4 = 400
static const int OFF_B1   = 9304;            // 40
static const int OFF_WIH2 = 9344;            // 10*4*4 = 160
static const int OFF_WHH2 = 9504;            // 4*4*4 = 64
static const int OFF_B2   = 9568;            // 16
static const int W_TOTAL  = 9584;
// per-thread state columns [elem][NT]
static const int ST_HS0 = 0;                 // 26*NT (26th = pad, dead)
static const int ST_CS0 = 26 * NT;           // 26*NT
static const int ST_HS1 = 52 * NT;           // 10*NT
static const int ST_CS1 = 62 * NT;
static const int ST_HS2 = 72 * NT;           // 4*NT
static const int ST_CS2 = 76 * NT;
static const int ST_TOTAL = 80 * NT;
static const int SMEM_BYTES = (W_TOTAL + ST_TOTAL) * 4;   // 79,296 B -> 2 blk/SM

// ---------------- weight packers --------------------------------------------
// src Wih: [4H, DIN] row-major (torch gate order i,f,g,o).
// dst[(k*HP+j)*4+g] = (j < H) ? src[(g*H+j)*DIN+k] : 0
template <int DIN, int H, int HP>
__device__ void packw(float* dst, const float* __restrict__ src, int tid) {
    const int n = DIN * HP * 4;
    for (int idx = tid; idx < n; idx += NT) {
        int g = idx & 3, jk = idx >> 2;
        int j = jk % HP, k = jk / HP;
        dst[idx] = (j < H) ? src[(g * H + j) * DIN + k] : 0.0f;
    }
}
template <int H, int HP>
__device__ void packb(float* dst, const float* __restrict__ src, int tid) {
    for (int idx = tid; idx < 4 * HP; idx += NT) {
        int g = idx & 3, j = idx >> 2;
        dst[idx] = (j < H) ? src[g * H + j] : 0.0f;
    }
}

// ---------------- one LSTM layer step, gate-packed f32x2, j-paired ----------
// xs: DIN splatted inputs (registers, hoisted). hsp: scratch for H splats.
// hs/cs: smem state columns (pointer already +tid, stride NT).
// Computes HP units (HP even, HP>=H); units >= H are dead padding.
template <int DIN, int H, int HP>
__device__ __forceinline__ void step2(
    const u64* xs,
    const float* swih, const float* swhh, const float* sbias,
    float* hs, float* cs, u64* hsp)
{
#pragma unroll
    for (int k = 0; k < H; k++) hsp[k] = splat2(hs[k * NT]);

    const ulonglong2* wih = reinterpret_cast<const ulonglong2*>(swih);
    const ulonglong2* whh = reinterpret_cast<const ulonglong2*>(swhh);
    const ulonglong2* bb  = reinterpret_cast<const ulonglong2*>(sbias);

#pragma unroll 1
    for (int jt = 0; jt < HP; jt += 2) {
        ulonglong2 b0 = bb[jt];
        ulonglong2 b1 = bb[jt + 1];
        u64 a01_0 = b0.x, a23_0 = b0.y;      // unit jt:   {i,f}, {g,o}
        u64 a01_1 = b1.x, a23_1 = b1.y;      // unit jt+1: {i,f}, {g,o}
#pragma unroll
        for (int k = 0; k < DIN; k++) {
            ulonglong2 w0 = wih[k * HP + jt];        // LDS.128 broadcast
            ulonglong2 w1 = wih[k * HP + jt + 1];    // independent stream
            u64 xv = xs[k];
            a01_0 = fma2(xv, w0.x, a01_0);
            a23_0 = fma2(xv, w0.y, a23_0);
            a01_1 = fma2(xv, w1.x, a01_1);
            a23_1 = fma2(xv, w1.y, a23_1);
        }
#pragma unroll
        for (int k = 0; k < H; k++) {
            ulonglong2 w0 = whh[k * HP + jt];
            ulonglong2 w1 = whh[k * HP + jt + 1];
            u64 hv = hsp[k];
            a01_0 = fma2(hv, w0.x, a01_0);
            a23_0 = fma2(hv, w0.y, a23_0);
            a01_1 = fma2(hv, w1.x, a01_1);
            a23_1 = fma2(hv, w1.y, a23_1);
        }
        {
            float ai, af, ag, ao;
            unpack2(a01_0, ai, af);
            unpack2(a23_0, ag, ao);
            float c = fmaf(sigf(af), cs[jt * NT], sigf(ai) * tanhfast(ag));
            cs[jt * NT] = c;
            hs[jt * NT] = sigf(ao) * tanhfast(c);
        }
        {
            float ai, af, ag, ao;
            unpack2(a01_1, ai, af);
            unpack2(a23_1, ag, ao);
            float c = fmaf(sigf(af), cs[(jt + 1) * NT], sigf(ai) * tanhfast(ag));
            cs[(jt + 1) * NT] = c;
            hs[(jt + 1) * NT] = sigf(ao) * tanhfast(c);
        }
    }
}

// ---------------- tower body ------------------------------------------------
template <int T>
__device__ __forceinline__ void run_tower(
    const float* __restrict__ x_in,
    const float* __restrict__ Wih0, const float* __restrict__ Whh0,
    const float* __restrict__ b0,
    const float* __restrict__ Wih1, const float* __restrict__ Whh1,
    const float* __restrict__ b1,
    const float* __restrict__ Wih2, const float* __restrict__ Whh2,
    const float* __restrict__ b2,
    float* __restrict__ hout, int blockbase, float* sm)
{
    const int tid = threadIdx.x;

    packw<50, 25, H0P>(sm + OFF_WIH0, Wih0, tid);
    packw<25, 25, H0P>(sm + OFF_WHH0, Whh0, tid);
    packb<25, H0P>(sm + OFF_B0, b0, tid);
    packw<25, 10, 10>(sm + OFF_WIH1, Wih1, tid);
    packw<10, 10, 10>(sm + OFF_WHH1, Whh1, tid);
    packb<10, 10>(sm + OFF_B1, b1, tid);
    packw<10, 4, 4>(sm + OFF_WIH2, Wih2, tid);
    packw<4, 4, 4>(sm + OFF_WHH2, Whh2, tid);
    packb<4, 4>(sm + OFF_B2, b2, tid);
    __syncthreads();

    float* st  = sm + W_TOTAL;
    float* hs0 = st + ST_HS0 + tid;
    float* cs0 = st + ST_CS0 + tid;
    float* hs1 = st + ST_HS1 + tid;
    float* cs1 = st + ST_CS1 + tid;
    float* hs2 = st + ST_HS2 + tid;
    float* cs2 = st + ST_CS2 + tid;

#pragma unroll
    for (int j = 0; j < H0P; j++) { hs0[j * NT] = 0.0f; cs0[j * NT] = 0.0f; }
#pragma unroll
    for (int j = 0; j < 10; j++) { hs1[j * NT] = 0.0f; cs1[j * NT] = 0.0f; }
#pragma unroll
    for (int j = 0; j < 4; j++)  { hs2[j * NT] = 0.0f; cs2[j * NT] = 0.0f; }

    const int row = blockbase * NT + tid;
    const float* xrow = x_in + (size_t)row * T * 50;

    u64 xs[50];
    u64 hsp[25];

    for (int t = 0; t < T; t++) {
        const float2* xp = reinterpret_cast<const float2*>(xrow + t * 50);
#pragma unroll
        for (int k2 = 0; k2 < 25; k2++) {
            float2 v = __ldg(xp + k2);
            xs[2 * k2]     = splat2(v.x);
            xs[2 * k2 + 1] = splat2(v.y);
        }
        step2<50, 25, H0P>(xs, sm + OFF_WIH0, sm + OFF_WHH0, sm + OFF_B0,
                           hs0, cs0, hsp);
#pragma unroll
        for (int k = 0; k < 25; k++) xs[k] = splat2(hs0[k * NT]);
        step2<25, 10, 10>(xs, sm + OFF_WIH1, sm + OFF_WHH1, sm + OFF_B1,
                          hs1, cs1, hsp);
#pragma unroll
        for (int k = 0; k < 10; k++) xs[k] = splat2(hs1[k * NT]);
        step2<10, 4, 4>(xs, sm + OFF_WIH2, sm + OFF_WHH2, sm + OFF_B2,
                        hs2, cs2, hsp);
    }

#pragma unroll
    for (int j = 0; j < 4; j++) hout[row * 4 + j] = hs2[j * NT];
}

// ---------------- merged dual-tower kernel ----------------------------------
__global__ void __launch_bounds__(NT)
towers_kernel(
    const float* __restrict__ q, const float* __restrict__ p,
    const float* qa0, const float* qa1, const float* qa2,
    const float* qa3, const float* qa4, const float* qa5,
    const float* qa6, const float* qa7, const float* qa8,
    const float* pa0, const float* pa1, const float* pa2,
    const float* pa3, const float* pa4, const float* pa5,
    const float* pa6, const float* pa7, const float* pa8)
{
    extern __shared__ float sm[];
    if (blockIdx.x < BTOT / NT) {
        // p tower first (T=50, long blocks start in wave 1)
        run_tower<50>(p, pa0, pa1, pa2, pa3, pa4, pa5, pa6, pa7, pa8,
                      g_hp, blockIdx.x, sm);
    } else {
        run_tower<12>(q, qa0, qa1, qa2, qa3, qa4, qa5, qa6, qa7, qa8,
                      g_hq, blockIdx.x - BTOT / NT, sm);
    }
}

// ---------------- combine: scores -> softmax --------------------------------
__global__ void __launch_bounds__(256)
combine_kernel(const float* __restrict__ fW, const float* __restrict__ fb,
               float* __restrict__ out)
{
    int row = blockIdx.x * blockDim.x + threadIdx.x;
    float s0 = g_hq[row * 4 + 0] * g_hp[row * 4 + 0];
    float s1 = g_hq[row * 4 + 1] * g_hp[row * 4 + 1];
    float s2 = g_hq[row * 4 + 2] * g_hp[row * 4 + 2];
    float s3 = g_hq[row * 4 + 3] * g_hp[row * 4 + 3];
    float l0 = __ldg(fb + 0) + __ldg(fW + 0) * s0 + __ldg(fW + 1) * s1
                             + __ldg(fW + 2) * s2 + __ldg(fW + 3) * s3;
    float l1 = __ldg(fb + 1) + __ldg(fW + 4) * s0 + __ldg(fW + 5) * s1
                             + __ldg(fW + 6) * s2 + __ldg(fW + 7) * s3;
    float m = fmaxf(l0, l1);
    float e0 = __expf(l0 - m);
    float e1 = __expf(l1 - m);
    float inv = __fdividef(1.0f, e0 + e1);
    out[row * 2 + 0] = e0 * inv;
    out[row * 2 + 1] = e1 * inv;
}

// ---------------- launch ----------------------------------------------------
extern "C" void kernel_launch(void* const* d_in, const int* in_sizes, int n_in,
                              void* d_out, int out_size)
{
    const float* q  = (const float*)d_in[0];
    const float* p  = (const float*)d_in[1];
    const float* qw[9];
    const float* pw[9];
    for (int i = 0; i < 9; i++) qw[i] = (const float*)d_in[2 + i];
    for (int i = 0; i < 9; i++) pw[i] = (const float*)d_in[11 + i];
    const float* fW = (const float*)d_in[20];
    const float* fb = (const float*)d_in[21];
    float* out = (float*)d_out;

    cudaFuncSetAttribute(towers_kernel,
                         cudaFuncAttributeMaxDynamicSharedMemorySize, SMEM_BYTES);

    towers_kernel<<<2 * (BTOT / NT), NT, SMEM_BYTES>>>(
        q, p,
        qw[0], qw[1], qw[2], qw[3], qw[4], qw[5], qw[6], qw[7], qw[8],
        pw[0], pw[1], pw[2], pw[3], pw[4], pw[5], pw[6], pw[7], pw[8]);
    combine_kernel<<<BTOT / 256, 256>>>(fW, fb, out);
}